// round 1
// baseline (speedup 1.0000x reference)
#include <cuda_runtime.h>
#include <math.h>

#define N_NODES 100000
#define N_EDGES 1600000
#define TOT_E   (N_EDGES + N_NODES)
#define HC 128           // HEADS * OUT_CH
#define IN_CH 64

// ---------------- scratch (device globals; allocation-free) ----------------
__device__ float g_h[(size_t)N_NODES * HC];      // 51.2 MB  transformed features
__device__ float g_asrc[N_NODES * 4];            // per-node att halves
__device__ float g_adst[N_NODES * 4];
__device__ float g_m[N_NODES * 4];               // segment max
__device__ float g_denom[N_NODES * 4];           // segment sum of exp
__device__ float g_ex[(size_t)TOT_E * 4];        // 27.2 MB  per-edge exp(e-m)
__device__ float g_agg[(size_t)N_NODES * HC];    // 51.2 MB  aggregated output

// ---------------- helpers ----------------
__device__ __forceinline__ float lrelu(float v) { return v > 0.f ? v : 0.2f * v; }

// float atomic max via int/uint monotonicity trick
__device__ __forceinline__ void atomicMaxF(float* addr, float v) {
    if (v >= 0.f) atomicMax((int*)addr, __float_as_int(v));
    else          atomicMin((unsigned int*)addr, __float_as_uint(v));
}

__device__ __forceinline__ void red_add_v4(float* addr, float4 v) {
    asm volatile("red.global.add.v4.f32 [%0], {%1,%2,%3,%4};"
                 :: "l"(addr), "f"(v.x), "f"(v.y), "f"(v.z), "f"(v.w)
                 : "memory");
}

// ---------------- kernels ----------------
__global__ void k_init() {
    int i = blockIdx.x * blockDim.x + threadIdx.x;
    if (i < N_NODES * HC) g_agg[i] = 0.f;
    if (i < N_NODES * 4) {
        g_denom[i] = 0.f;
        g_m[i] = __int_as_float(0xff800000);   // -inf
    }
}

// h = x @ W  (fp32, smem-tiled, persistent grid), fused att_src/att_dst reduction
__global__ void k_gemm(const float* __restrict__ x, const float* __restrict__ W,
                       const float* __restrict__ att_src, const float* __restrict__ att_dst) {
    __shared__ float Ws[IN_CH * HC];     // 32 KB
    __shared__ float xs[4 * IN_CH];      // 4 nodes per tile
    const int tid = threadIdx.x;         // 256 threads

    for (int i = tid; i < IN_CH * HC; i += 256) Ws[i] = W[i];

    const int p    = tid >> 7;           // 0..1
    const int ch   = tid & 127;          // output channel
    const int lane = tid & 31;
    const int head = ch >> 5;
    const float as = att_src[ch];
    const float ad = att_dst[ch];

    for (int base = blockIdx.x * 4; base < N_NODES; base += gridDim.x * 4) {
        __syncthreads();
        {   // stage 4 rows of x
            int nl = tid >> 6, kk = tid & 63;
            int nn = base + nl;
            xs[tid] = (nn < N_NODES) ? x[nn * IN_CH + kk] : 0.f;
        }
        __syncthreads();

        const int n0 = base + p, n1 = base + p + 2;
        float acc0 = 0.f, acc1 = 0.f;
        const float* x0 = &xs[p * IN_CH];
        const float* x1 = &xs[(p + 2) * IN_CH];
        #pragma unroll
        for (int k = 0; k < IN_CH; k++) {
            float w = Ws[k * HC + ch];
            acc0 += x0[k] * w;
            acc1 += x1[k] * w;
        }
        if (n0 < N_NODES) g_h[(size_t)n0 * HC + ch] = acc0;
        if (n1 < N_NODES) g_h[(size_t)n1 * HC + ch] = acc1;

        // warp = exactly one head's 32 channels -> shuffle-reduce att halves
        float s0 = acc0 * as, d0 = acc0 * ad, s1 = acc1 * as, d1 = acc1 * ad;
        #pragma unroll
        for (int o = 16; o > 0; o >>= 1) {
            s0 += __shfl_xor_sync(0xffffffffu, s0, o);
            d0 += __shfl_xor_sync(0xffffffffu, d0, o);
            s1 += __shfl_xor_sync(0xffffffffu, s1, o);
            d1 += __shfl_xor_sync(0xffffffffu, d1, o);
        }
        if (lane == 0) {
            if (n0 < N_NODES) { g_asrc[n0 * 4 + head] = s0; g_adst[n0 * 4 + head] = d0; }
            if (n1 < N_NODES) { g_asrc[n1 * 4 + head] = s1; g_adst[n1 * 4 + head] = d1; }
        }
    }
}

// pass 1: segment max of leaky(a_src[s] + a_dst[d]) over dst
__global__ void k_max(const int* __restrict__ ei) {
    int i = blockIdx.x * blockDim.x + threadIdx.x;
    if (i >= TOT_E) return;
    int s, d;
    if (i < N_EDGES) { s = ei[i]; d = ei[N_EDGES + i]; }
    else             { s = d = i - N_EDGES; }
    float4 as = ((const float4*)g_asrc)[s];
    float4 ad = ((const float4*)g_adst)[d];
    atomicMaxF(&g_m[d * 4 + 0], lrelu(as.x + ad.x));
    atomicMaxF(&g_m[d * 4 + 1], lrelu(as.y + ad.y));
    atomicMaxF(&g_m[d * 4 + 2], lrelu(as.z + ad.z));
    atomicMaxF(&g_m[d * 4 + 3], lrelu(as.w + ad.w));
}

// pass 2: ex = exp(e - m[dst]); denom = segment_sum(ex)
__global__ void k_exp(const int* __restrict__ ei) {
    int i = blockIdx.x * blockDim.x + threadIdx.x;
    if (i >= TOT_E) return;
    int s, d;
    if (i < N_EDGES) { s = ei[i]; d = ei[N_EDGES + i]; }
    else             { s = d = i - N_EDGES; }
    float4 as = ((const float4*)g_asrc)[s];
    float4 ad = ((const float4*)g_adst)[d];
    float4 m4 = ((const float4*)g_m)[d];
    float4 ex;
    ex.x = __expf(lrelu(as.x + ad.x) - m4.x);
    ex.y = __expf(lrelu(as.y + ad.y) - m4.y);
    ex.z = __expf(lrelu(as.z + ad.z) - m4.z);
    ex.w = __expf(lrelu(as.w + ad.w) - m4.w);
    ((float4*)g_ex)[i] = ex;
    red_add_v4(&g_denom[d * 4], ex);
}

// pass 3: one warp per edge: agg[dst] += h[src] * alpha
__global__ void k_agg(const int* __restrict__ ei) {
    int wid  = (blockIdx.x * blockDim.x + threadIdx.x) >> 5;
    int lane = threadIdx.x & 31;
    if (wid >= TOT_E) return;
    int s, d;
    if (wid < N_EDGES) { s = ei[wid]; d = ei[N_EDGES + wid]; }
    else               { s = d = wid - N_EDGES; }
    int head = lane >> 3;                         // 8 lanes per head (32 ch = 8*float4)
    float ex  = g_ex[(size_t)wid * 4 + head];
    float den = g_denom[d * 4 + head];
    float alpha = ex / (den + 1e-16f);
    float4 hv = ((const float4*)g_h)[(size_t)s * 32 + lane];
    hv.x *= alpha; hv.y *= alpha; hv.z *= alpha; hv.w *= alpha;
    red_add_v4(&g_agg[(size_t)d * HC + lane * 4], hv);
}

// pass 4: out = log_softmax(agg + bias) per row of 128
__global__ void k_lsm(const float* __restrict__ bias, float* __restrict__ out) {
    int wid  = (blockIdx.x * blockDim.x + threadIdx.x) >> 5;
    int lane = threadIdx.x & 31;
    if (wid >= N_NODES) return;
    float4 v = ((const float4*)g_agg)[(size_t)wid * 32 + lane];
    float4 b = ((const float4*)bias)[lane];
    v.x += b.x; v.y += b.y; v.z += b.z; v.w += b.w;
    float mx = fmaxf(fmaxf(v.x, v.y), fmaxf(v.z, v.w));
    #pragma unroll
    for (int o = 16; o > 0; o >>= 1) mx = fmaxf(mx, __shfl_xor_sync(0xffffffffu, mx, o));
    float sm = __expf(v.x - mx) + __expf(v.y - mx) + __expf(v.z - mx) + __expf(v.w - mx);
    #pragma unroll
    for (int o = 16; o > 0; o >>= 1) sm += __shfl_xor_sync(0xffffffffu, sm, o);
    float lse = mx + __logf(sm);
    float4 r = make_float4(v.x - lse, v.y - lse, v.z - lse, v.w - lse);
    ((float4*)out)[(size_t)wid * 32 + lane] = r;
}

// ---------------- launch ----------------
extern "C" void kernel_launch(void* const* d_in, const int* in_sizes, int n_in,
                              void* d_out, int out_size) {
    const float* x       = (const float*)d_in[0];
    const int*   ei      = (const int*)d_in[1];
    const float* W       = (const float*)d_in[2];
    const float* att_src = (const float*)d_in[3];
    const float* att_dst = (const float*)d_in[4];
    const float* bias    = (const float*)d_in[5];
    float* out = (float*)d_out;

    k_init<<<(N_NODES * HC + 255) / 256, 256>>>();
    k_gemm<<<1024, 256>>>(x, W, att_src, att_dst);
    k_max<<<(TOT_E + 255) / 256, 256>>>(ei);
    k_exp<<<(TOT_E + 255) / 256, 256>>>(ei);
    k_agg<<<((size_t)TOT_E * 32 + 255) / 256, 256>>>(ei);
    k_lsm<<<(N_NODES * 32 + 255) / 256, 256>>>(bias, out);
}

// round 4
// speedup vs baseline: 2.2771x; 2.2771x over previous
#include <cuda_runtime.h>
#include <math.h>

#define N_NODES 100000
#define N_EDGES 1600000
#define HC 128           // HEADS * OUT_CH
#define IN_CH 64
#define SCAN_CHUNK 512
#define SCAN_BLOCKS ((N_NODES + SCAN_CHUNK - 1) / SCAN_CHUNK)   // 196

// ---------------- scratch (device globals; allocation-free) ----------------
__device__ float g_h[(size_t)N_NODES * HC];      // 51.2 MB transformed features
__device__ float g_asrc[N_NODES * 4];
__device__ float g_adst[N_NODES * 4];
__device__ int   g_cnt[N_NODES];                 // in-degree (edges only)
__device__ int   g_offs[N_NODES + 1];            // CSR row starts
__device__ int   g_cursor[N_NODES];              // scatter cursors
__device__ int   g_part[SCAN_BLOCKS];            // scan partials
__device__ int   g_csr[N_EDGES];                 // src node per bucketed edge

// ---------------- helpers ----------------
__device__ __forceinline__ float lrelu(float v) { return v > 0.f ? v : 0.2f * v; }
__device__ __forceinline__ float4 expl4(float4 a, float4 b) {
    float4 r;
    r.x = __expf(lrelu(a.x + b.x));
    r.y = __expf(lrelu(a.y + b.y));
    r.z = __expf(lrelu(a.z + b.z));
    r.w = __expf(lrelu(a.w + b.w));
    return r;
}
__device__ __forceinline__ float pick4(float4 v, int h) {
    return h == 0 ? v.x : (h == 1 ? v.y : (h == 2 ? v.z : v.w));
}

// ---------------- kernels ----------------
__global__ void k_zero() {
    int i = blockIdx.x * blockDim.x + threadIdx.x;
    if (i < N_NODES) g_cnt[i] = 0;
}

// h = x @ W with 4ch x 4node register blocking; fused att halves
__global__ void k_gemm(const float* __restrict__ x, const float* __restrict__ W,
                       const float* __restrict__ att_src, const float* __restrict__ att_dst) {
    __shared__ float Ws[IN_CH * HC];   // [k][ch] 32 KB
    __shared__ float xs[IN_CH * 32];   // [k][n]   8 KB
    const int tid = threadIdx.x;       // 256

    for (int i = tid; i < IN_CH * HC; i += 256) Ws[i] = W[i];

    const int cg = tid & 31;           // channel-quad index (ch = cg*4)
    const int ng = tid >> 5;           // node-quad index (4 nodes)
    const int head = cg >> 3;
    const float4 As = ((const float4*)att_src)[cg];
    const float4 Ad = ((const float4*)att_dst)[cg];

    for (int tile = blockIdx.x * 32; tile < N_NODES; tile += gridDim.x * 32) {
        __syncthreads();
        {   // stage 32 nodes of x into [k][n] layout
            int n = tid >> 3, kq = tid & 7;
            float4 v0 = ((const float4*)x)[(size_t)(tile + n) * 16 + kq];
            float4 v1 = ((const float4*)x)[(size_t)(tile + n) * 16 + kq + 8];
            xs[(kq * 4 + 0) * 32 + n] = v0.x;
            xs[(kq * 4 + 1) * 32 + n] = v0.y;
            xs[(kq * 4 + 2) * 32 + n] = v0.z;
            xs[(kq * 4 + 3) * 32 + n] = v0.w;
            xs[((kq + 8) * 4 + 0) * 32 + n] = v1.x;
            xs[((kq + 8) * 4 + 1) * 32 + n] = v1.y;
            xs[((kq + 8) * 4 + 2) * 32 + n] = v1.z;
            xs[((kq + 8) * 4 + 3) * 32 + n] = v1.w;
        }
        __syncthreads();

        float4 acc0 = {0,0,0,0}, acc1 = {0,0,0,0}, acc2 = {0,0,0,0}, acc3 = {0,0,0,0};
        #pragma unroll
        for (int k = 0; k < IN_CH; k++) {
            float4 w  = ((const float4*)Ws)[k * 32 + cg];
            float4 xv = ((const float4*)xs)[k * 8 + ng];
            acc0.x += w.x * xv.x; acc0.y += w.y * xv.x; acc0.z += w.z * xv.x; acc0.w += w.w * xv.x;
            acc1.x += w.x * xv.y; acc1.y += w.y * xv.y; acc1.z += w.z * xv.y; acc1.w += w.w * xv.y;
            acc2.x += w.x * xv.z; acc2.y += w.y * xv.z; acc2.z += w.z * xv.z; acc2.w += w.w * xv.z;
            acc3.x += w.x * xv.w; acc3.y += w.y * xv.w; acc3.z += w.z * xv.w; acc3.w += w.w * xv.w;
        }
        const int n0 = tile + ng * 4;
        ((float4*)g_h)[(size_t)(n0 + 0) * 32 + cg] = acc0;
        ((float4*)g_h)[(size_t)(n0 + 1) * 32 + cg] = acc1;
        ((float4*)g_h)[(size_t)(n0 + 2) * 32 + cg] = acc2;
        ((float4*)g_h)[(size_t)(n0 + 3) * 32 + cg] = acc3;

        // attention halves: reduce 8 lanes (one head) per node
        float ps[4], pd[4];
        ps[0] = acc0.x*As.x + acc0.y*As.y + acc0.z*As.z + acc0.w*As.w;
        ps[1] = acc1.x*As.x + acc1.y*As.y + acc1.z*As.z + acc1.w*As.w;
        ps[2] = acc2.x*As.x + acc2.y*As.y + acc2.z*As.z + acc2.w*As.w;
        ps[3] = acc3.x*As.x + acc3.y*As.y + acc3.z*As.z + acc3.w*As.w;
        pd[0] = acc0.x*Ad.x + acc0.y*Ad.y + acc0.z*Ad.z + acc0.w*Ad.w;
        pd[1] = acc1.x*Ad.x + acc1.y*Ad.y + acc1.z*Ad.z + acc1.w*Ad.w;
        pd[2] = acc2.x*Ad.x + acc2.y*Ad.y + acc2.z*Ad.z + acc2.w*Ad.w;
        pd[3] = acc3.x*Ad.x + acc3.y*Ad.y + acc3.z*Ad.z + acc3.w*Ad.w;
        #pragma unroll
        for (int o = 1; o < 8; o <<= 1) {
            #pragma unroll
            for (int j = 0; j < 4; j++) {
                ps[j] += __shfl_xor_sync(0xffffffffu, ps[j], o);
                pd[j] += __shfl_xor_sync(0xffffffffu, pd[j], o);
            }
        }
        if ((cg & 7) == 0) {
            #pragma unroll
            for (int j = 0; j < 4; j++) {
                g_asrc[(n0 + j) * 4 + head] = ps[j];
                g_adst[(n0 + j) * 4 + head] = pd[j];
            }
        }
    }
}

__global__ void k_hist(const int* __restrict__ ei) {
    int i = blockIdx.x * blockDim.x + threadIdx.x;
    if (i < N_EDGES) atomicAdd(&g_cnt[ei[N_EDGES + i]], 1);
}

// scan step 1: per-chunk exclusive scan + partial totals
__global__ void k_scan1() {
    __shared__ int sm[SCAN_CHUNK];
    int b = blockIdx.x, t = threadIdx.x;        // 512 threads
    int i = b * SCAN_CHUNK + t;
    int v = (i < N_NODES) ? g_cnt[i] : 0;
    sm[t] = v;
    __syncthreads();
    #pragma unroll
    for (int o = 1; o < SCAN_CHUNK; o <<= 1) {
        int add = (t >= o) ? sm[t - o] : 0;
        __syncthreads();
        sm[t] += add;
        __syncthreads();
    }
    if (i < N_NODES) g_offs[i] = sm[t] - v;     // exclusive
    if (t == SCAN_CHUNK - 1) g_part[b] = sm[t];
}

// scan step 2: scan the 196 partials (one block)
__global__ void k_scan2() {
    __shared__ int sm[256];
    int t = threadIdx.x;
    int v = (t < SCAN_BLOCKS) ? g_part[t] : 0;
    sm[t] = v;
    __syncthreads();
    #pragma unroll
    for (int o = 1; o < 256; o <<= 1) {
        int add = (t >= o) ? sm[t - o] : 0;
        __syncthreads();
        sm[t] += add;
        __syncthreads();
    }
    if (t < SCAN_BLOCKS) g_part[t] = sm[t] - v; // exclusive
}

// scan step 3: add partial offsets, init cursors
__global__ void k_scan3() {
    int i = blockIdx.x * blockDim.x + threadIdx.x;
    if (i < N_NODES) {
        int off = g_offs[i] + g_part[i / SCAN_CHUNK];
        g_offs[i] = off;
        g_cursor[i] = off;
    }
    if (i == 0) g_offs[N_NODES] = N_EDGES;
}

__global__ void k_scatter(const int* __restrict__ ei) {
    int i = blockIdx.x * blockDim.x + threadIdx.x;
    if (i >= N_EDGES) return;
    int d = ei[N_EDGES + i];
    int pos = atomicAdd(&g_cursor[d], 1);
    g_csr[pos] = ei[i];
}

// one warp per dst: denom + weighted aggregation + bias + log_softmax
__global__ void k_fused(const float* __restrict__ bias, float* __restrict__ out) {
    int d    = (blockIdx.x * blockDim.x + threadIdx.x) >> 5;
    int lane = threadIdx.x & 31;
    if (d >= N_NODES) return;
    const int head = lane >> 3;
    const int beg = g_offs[d], end = g_offs[d + 1];

    const float4 ad4 = ((const float4*)g_adst)[d];
    const float4 as_d = ((const float4*)g_asrc)[d];

    // denominator (includes self loop), unshifted exp (scores are O(3))
    float4 den = {0,0,0,0};
    for (int e = beg + lane; e < end; e += 32) {
        float4 as = ((const float4*)g_asrc)[g_csr[e]];
        float4 ex = expl4(as, ad4);
        den.x += ex.x; den.y += ex.y; den.z += ex.z; den.w += ex.w;
    }
    #pragma unroll
    for (int o = 16; o > 0; o >>= 1) {
        den.x += __shfl_xor_sync(0xffffffffu, den.x, o);
        den.y += __shfl_xor_sync(0xffffffffu, den.y, o);
        den.z += __shfl_xor_sync(0xffffffffu, den.z, o);
        den.w += __shfl_xor_sync(0xffffffffu, den.w, o);
    }
    float4 eself = expl4(as_d, ad4);
    den.x += eself.x; den.y += eself.y; den.z += eself.z; den.w += eself.w;
    float4 inv4;
    inv4.x = 1.f / (den.x + 1e-16f);
    inv4.y = 1.f / (den.y + 1e-16f);
    inv4.z = 1.f / (den.z + 1e-16f);
    inv4.w = 1.f / (den.w + 1e-16f);

    // self-loop contribution
    float al_self = pick4(eself, head) * pick4(inv4, head);
    float4 hv = ((const float4*)g_h)[(size_t)d * 32 + lane];
    float4 acc;
    acc.x = hv.x * al_self; acc.y = hv.y * al_self;
    acc.z = hv.z * al_self; acc.w = hv.w * al_self;

    // edge contributions, 32-edge chunks: each lane computes alpha for one
    // edge, then all lanes cooperate on each edge's 128 channels.
    for (int base = beg; base < end; base += 32) {
        int e = base + lane;
        int s_my = 0;
        float4 al4 = {0,0,0,0};
        if (e < end) {
            s_my = g_csr[e];
            float4 as = ((const float4*)g_asrc)[s_my];
            float4 ex = expl4(as, ad4);
            al4.x = ex.x * inv4.x; al4.y = ex.y * inv4.y;
            al4.z = ex.z * inv4.z; al4.w = ex.w * inv4.w;
        }
        int n = min(32, end - base);
        for (int k = 0; k < n; k++) {
            int s = __shfl_sync(0xffffffffu, s_my, k);
            float a0 = __shfl_sync(0xffffffffu, al4.x, k);
            float a1 = __shfl_sync(0xffffffffu, al4.y, k);
            float a2 = __shfl_sync(0xffffffffu, al4.z, k);
            float a3 = __shfl_sync(0xffffffffu, al4.w, k);
            float al = head == 0 ? a0 : (head == 1 ? a1 : (head == 2 ? a2 : a3));
            float4 h4 = ((const float4*)g_h)[(size_t)s * 32 + lane];
            acc.x += h4.x * al; acc.y += h4.y * al;
            acc.z += h4.z * al; acc.w += h4.w * al;
        }
    }

    // bias + log_softmax over 128 channels
    float4 b = ((const float4*)bias)[lane];
    acc.x += b.x; acc.y += b.y; acc.z += b.z; acc.w += b.w;
    float mx = fmaxf(fmaxf(acc.x, acc.y), fmaxf(acc.z, acc.w));
    #pragma unroll
    for (int o = 16; o > 0; o >>= 1) mx = fmaxf(mx, __shfl_xor_sync(0xffffffffu, mx, o));
    float sm = __expf(acc.x - mx) + __expf(acc.y - mx) + __expf(acc.z - mx) + __expf(acc.w - mx);
    #pragma unroll
    for (int o = 16; o > 0; o >>= 1) sm += __shfl_xor_sync(0xffffffffu, sm, o);
    float lse = mx + __logf(sm);
    float4 r = make_float4(acc.x - lse, acc.y - lse, acc.z - lse, acc.w - lse);
    ((float4*)out)[(size_t)d * 32 + lane] = r;
}

// ---------------- launch ----------------
extern "C" void kernel_launch(void* const* d_in, const int* in_sizes, int n_in,
                              void* d_out, int out_size) {
    const float* x       = (const float*)d_in[0];
    const int*   ei      = (const int*)d_in[1];
    const float* W       = (const float*)d_in[2];
    const float* att_src = (const float*)d_in[3];
    const float* att_dst = (const float*)d_in[4];
    const float* bias    = (const float*)d_in[5];
    float* out = (float*)d_out;

    k_zero<<<(N_NODES + 255) / 256, 256>>>();
    k_gemm<<<1184, 256>>>(x, W, att_src, att_dst);
    k_hist<<<(N_EDGES + 255) / 256, 256>>>(ei);
    k_scan1<<<SCAN_BLOCKS, SCAN_CHUNK>>>();
    k_scan2<<<1, 256>>>();
    k_scan3<<<(N_NODES + 255) / 256, 256>>>();
    k_scatter<<<(N_EDGES + 255) / 256, 256>>>(ei);
    k_fused<<<(N_NODES * 32 + 255) / 256, 256>>>(bias, out);
}